// round 15
// baseline (speedup 1.0000x reference)
#include <cuda_runtime.h>
#include <cuda_fp16.h>
#include <math.h>
#include <cstdint>

// Problem constants
#define B_  8
#define C_  512
#define T_  4096
#define O_  512
#define CK_ 1536
#define EPS 1e-8f

#define NKS16 (CK_ / 16)      // 96 k16-steps
#define NKP   (CK_ / 32)      // 48 k32-steps
#define NT8   (T_ / 8)        // 512 n8 columns

#define DSTAGE 4              // cp.async ring depth per warp
#define STAGE_BYTES 2048      // 4 n8 * 32 lanes * 16B
#define GEMM_SMEM (8 * DSTAGE * STAGE_BYTES)   // 64 KB

// Scratch
__device__ float g_n2[B_ * T_];
__device__ float g_d [B_ * T_];
__device__ float g_s [B_ * 3 * T_];
__device__ uint4 g_wf[NKS16 * 32 * 32];             // W fp16 A-frags
__device__ uint4 g_xf[(size_t)B_ * NT8 * NKP * 32]; // Xs fp16 B-frags (~100MB)

__device__ __forceinline__ uint32_t packh2(float a, float b) {
    __half2 h = __floats2half2_rn(a, b);
    return *reinterpret_cast<uint32_t*>(&h);
}

__device__ __forceinline__ uint32_t smem_u32(const void* p) {
    uint32_t a;
    asm("{ .reg .u64 t; cvta.to.shared.u64 t, %1; cvt.u32.u64 %0, t; }"
        : "=r"(a) : "l"(p));
    return a;
}

__device__ __forceinline__ void mma_16816(float* d, const uint32_t* a,
                                          uint32_t b0, uint32_t b1) {
    asm volatile(
        "mma.sync.aligned.m16n8k16.row.col.f32.f16.f16.f32 "
        "{%0,%1,%2,%3}, {%4,%5,%6,%7}, {%8,%9}, {%0,%1,%2,%3};"
        : "+f"(d[0]), "+f"(d[1]), "+f"(d[2]), "+f"(d[3])
        : "r"(a[0]), "r"(a[1]), "r"(a[2]), "r"(a[3]), "r"(b0), "r"(b1));
}

// ---------------------------------------------------------------------------
// Kernel 0: repack W [O, CK] -> fp16 A-fragment order.
// ---------------------------------------------------------------------------
__global__ void repack_w_kernel(const float* __restrict__ w) {
    const int idx  = blockIdx.x * 256 + threadIdx.x;
    const int lane = idx & 31;
    const int m16  = (idx >> 5) & 31;
    const int ks   = idx >> 10;
    const uint32_t r  = m16 * 16 + (lane >> 2);
    const uint32_t k0 = ks * 16 + (lane & 3) * 2;
    const float* p0 = w + r * CK_ + k0;
    const float* p1 = p0 + 8 * CK_;
    uint4 v;
    v.x = packh2(p0[0], p0[1]);
    v.y = packh2(p1[0], p1[1]);
    v.z = packh2(p0[8], p0[9]);
    v.w = packh2(p1[8], p1[9]);
    g_wf[idx] = v;
}

// ---------------------------------------------------------------------------
// Kernel 1: column stats, vectorized. grid (T/128, B), block 256.
// Warp covers 128 t (float4/lane); 8 warps split C into 64-chunks.
// t-1 stream via shfl_up; lane-0 halo through pre-decremented pointer
// (em1) so every loop index stays non-negative in 32-bit.
// ---------------------------------------------------------------------------
__global__ void sim_stats_kernel(const float* __restrict__ emb) {
    const int lane = threadIdx.x & 31;
    const int w    = threadIdx.x >> 5;          // c-partition 0..7
    const int t0   = blockIdx.x * 128;
    const int b    = blockIdx.y;
    const float* e = emb + (size_t)b * C_ * T_ + (uint32_t)w * 64 * T_
                   + (uint32_t)(t0 + lane * 4);
    const float* em1 = e - 1;                   // halo pointer (t0-1 base)

    float n2[4] = {0.f, 0.f, 0.f, 0.f};
    float dd[4] = {0.f, 0.f, 0.f, 0.f};
    const bool lead  = (lane == 0);
    const bool haveL = (t0 > 0);

    #pragma unroll 2
    for (uint32_t c = 0; c < 64; ++c) {
        float4 v = *reinterpret_cast<const float4*>(e + c * T_);
        float prevw = __shfl_up_sync(0xffffffffu, v.w, 1);
        if (lead) prevw = haveL ? em1[c * T_] : 0.f;
        n2[0] = fmaf(v.x, v.x, n2[0]);  dd[0] = fmaf(v.x, prevw, dd[0]);
        n2[1] = fmaf(v.y, v.y, n2[1]);  dd[1] = fmaf(v.y, v.x,   dd[1]);
        n2[2] = fmaf(v.z, v.z, n2[2]);  dd[2] = fmaf(v.z, v.y,   dd[2]);
        n2[3] = fmaf(v.w, v.w, n2[3]);  dd[3] = fmaf(v.w, v.z,   dd[3]);
    }

    __shared__ float sn[8][128], sd[8][128];
    #pragma unroll
    for (int j = 0; j < 4; ++j) {
        sn[w][lane * 4 + j] = n2[j];
        sd[w][lane * 4 + j] = dd[j];
    }
    __syncthreads();
    if (threadIdx.x < 128) {
        float a = 0.f, d2 = 0.f;
        #pragma unroll
        for (int j = 0; j < 8; ++j) { a += sn[j][threadIdx.x]; d2 += sd[j][threadIdx.x]; }
        g_n2[b * T_ + t0 + threadIdx.x] = a;
        g_d [b * T_ + t0 + threadIdx.x] = d2;
    }
}

// ---------------------------------------------------------------------------
// Kernel 2: finalize cosine sims (torch eps semantics).
// ---------------------------------------------------------------------------
__global__ void sim_finalize_kernel() {
    const int idx = blockIdx.x * 256 + threadIdx.x;
    if (idx >= B_ * T_) return;
    const int b = idx / T_;
    const int t = idx - b * T_;
    const float* n2 = g_n2 + b * T_;
    const float* d  = g_d  + b * T_;

    float nm    = fmaxf(sqrtf(n2[t]), EPS);
    float nprev = (t > 0)      ? fmaxf(sqrtf(n2[t - 1]), EPS) : EPS;
    float nnext = (t < T_ - 1) ? fmaxf(sqrtf(n2[t + 1]), EPS) : EPS;

    float* s = g_s + (size_t)b * 3 * T_;
    s[0 * T_ + t] = d[t] / (nm * nprev);
    s[1 * T_ + t] = n2[t] / (nm * nm);
    s[2 * T_ + t] = ((t < T_ - 1) ? d[t + 1] : 0.f) / (nm * nnext);
}

// ---------------------------------------------------------------------------
// Kernel 3: build Xs fragments. Interior blocks (n8 != 0, != NT8-1) take a
// predicate-free path; only edge blocks pay bounds checks.
// ---------------------------------------------------------------------------
__global__ __launch_bounds__(256)
void build_xs_kernel(const float* __restrict__ feat) {
    const int lane = threadIdx.x & 31;
    const int kp   = blockIdx.x * 8 + (threadIdx.x >> 5);
    const int n8   = blockIdx.y;
    const int b    = blockIdx.z;
    const int col  = lane >> 2;
    const int q    = lane & 3;
    const int t    = n8 * 8 + col;

    const float* fb = feat + (size_t)b * C_ * T_;
    const float  sg = g_s[(size_t)b * 3 * T_ + (uint32_t)(kp >> 4) * T_ + t];

    int i0 = kp * 32 + 2 * q;
    uint32_t c  = (uint32_t)i0 / 3u;
    int      k3 = i0 - 3 * (int)c;

    float x[8];
    if (n8 != 0 && n8 != NT8 - 1) {
        // interior: t-1 >= 7, t+1 <= T-2 -> no bounds checks
        const float* fp = fb + (uint32_t)(t - 1);
        #pragma unroll
        for (int p = 0; p < 4; ++p) {
            x[2*p] = __ldg(fp + c * (uint32_t)T_ + (uint32_t)k3) * sg;
            uint32_t cb = c; int kb = k3 + 1;
            if (kb == 3) { kb = 0; ++cb; }
            x[2*p+1] = __ldg(fp + cb * (uint32_t)T_ + (uint32_t)kb) * sg;
            k3 += 2; c += 2;
            if (k3 >= 3) { k3 -= 3; ++c; }
        }
    } else {
        #pragma unroll
        for (int p = 0; p < 4; ++p) {
            {
                int tt = t + k3 - 1;
                x[2*p] = ((unsigned)tt < (unsigned)T_)
                       ? __ldg(&fb[c * (uint32_t)T_ + (uint32_t)tt]) * sg : 0.f;
            }
            {
                uint32_t cb = c; int kb = k3 + 1;
                if (kb == 3) { kb = 0; ++cb; }
                int tt = t + kb - 1;
                x[2*p+1] = ((unsigned)tt < (unsigned)T_)
                         ? __ldg(&fb[cb * (uint32_t)T_ + (uint32_t)tt]) * sg : 0.f;
            }
            k3 += 2; c += 2;
            if (k3 >= 3) { k3 -= 3; ++c; }
        }
    }
    uint4 v;
    v.x = packh2(x[0], x[1]);
    v.y = packh2(x[2], x[3]);
    v.z = packh2(x[4], x[5]);
    v.w = packh2(x[6], x[7]);
    const uint32_t oidx = (((uint32_t)b * NT8 + n8) * NKP + kp) * 32 + lane;
    g_xf[oidx] = v;
}

// ---------------------------------------------------------------------------
// Kernel 4: MMA GEMM with per-warp cp.async B pipeline (unchanged from R13).
// ---------------------------------------------------------------------------
__global__ __launch_bounds__(256, 2)
void attconv_gemm_mma(float* __restrict__ out) {
    extern __shared__ uint32_t smem[];
    const int tid  = threadIdx.x;
    const int wid  = tid >> 5;
    const int lane = tid & 31;
    const int b       = blockIdx.z;
    const int m16Base = blockIdx.x * 4;
    const int n8Base  = blockIdx.y * 32 + wid * 4;

    const uint4* aW = g_wf + lane;
    const uint4* xB = g_xf + (size_t)((((uint32_t)b * NT8 + n8Base) * NKP) * 32 + lane);

    const uint32_t swbase = smem_u32(smem) + (uint32_t)wid * (DSTAGE * STAGE_BYTES)
                          + (uint32_t)lane * 16;

    auto issueStage = [&](int kp, int stage) {
        #pragma unroll
        for (int ni = 0; ni < 4; ++ni) {
            const uint32_t dst = swbase + (uint32_t)stage * STAGE_BYTES + ni * 512;
            const void* src = (const void*)(xB + (uint32_t)(ni * NKP + kp) * 32);
            asm volatile("cp.async.cg.shared.global [%0], [%1], 16;"
                         :: "r"(dst), "l"(src));
        }
        asm volatile("cp.async.commit_group;" ::: "memory");
    };

    issueStage(0, 0);
    issueStage(1, 1);
    issueStage(2, 2);

    float acc[4][4][4] = {};

    for (int kp = 0; kp < NKP; ++kp) {
        const int kpn = (kp + 3 < NKP) ? kp + 3 : NKP - 1;
        issueStage(kpn, (kp + 3) & (DSTAGE - 1));
        asm volatile("cp.async.wait_group 3;" ::: "memory");

        uint4 bv[4];
        const uint32_t sb = swbase + (uint32_t)(kp & (DSTAGE - 1)) * STAGE_BYTES;
        #pragma unroll
        for (int ni = 0; ni < 4; ++ni)
            asm volatile("ld.shared.v4.b32 {%0,%1,%2,%3}, [%4];"
                         : "=r"(bv[ni].x), "=r"(bv[ni].y),
                           "=r"(bv[ni].z), "=r"(bv[ni].w)
                         : "r"(sb + ni * 512));

        #pragma unroll
        for (int ks = 0; ks < 2; ++ks) {
            const uint32_t ksg = 2 * kp + ks;
            uint32_t af[4][4];
            #pragma unroll
            for (int mi = 0; mi < 4; ++mi) {
                uint4 a = __ldg(aW + ((ksg * 32 + m16Base + mi) << 5));
                af[mi][0] = a.x; af[mi][1] = a.y; af[mi][2] = a.z; af[mi][3] = a.w;
            }
            #pragma unroll
            for (int mi = 0; mi < 4; ++mi)
                #pragma unroll
                for (int ni = 0; ni < 4; ++ni) {
                    const uint32_t b0 = ks ? bv[ni].z : bv[ni].x;
                    const uint32_t b1 = ks ? bv[ni].w : bv[ni].y;
                    mma_16816(acc[mi][ni], af[mi], b0, b1);
                }
        }
    }

    float* outb = out + (size_t)b * O_ * T_;
    #pragma unroll
    for (int mi = 0; mi < 4; ++mi) {
        const uint32_t row0 = (m16Base + mi) * 16 + (lane >> 2);
        #pragma unroll
        for (int ni = 0; ni < 4; ++ni) {
            const uint32_t col = (n8Base + ni) * 8 + (lane & 3) * 2;
            float2 v0 = make_float2(acc[mi][ni][0], acc[mi][ni][1]);
            float2 v1 = make_float2(acc[mi][ni][2], acc[mi][ni][3]);
            *reinterpret_cast<float2*>(&outb[row0 * (uint32_t)T_ + col])        = v0;
            *reinterpret_cast<float2*>(&outb[(row0 + 8) * (uint32_t)T_ + col])  = v1;
        }
    }
}

// ---------------------------------------------------------------------------
// Launch: inputs in metadata order: feature, embedding, weight
// ---------------------------------------------------------------------------
extern "C" void kernel_launch(void* const* d_in, const int* in_sizes, int n_in,
                              void* d_out, int out_size) {
    const float* feature   = (const float*)d_in[0];
    const float* embedding = (const float*)d_in[1];
    const float* weight    = (const float*)d_in[2];
    float* out = (float*)d_out;

    cudaFuncSetAttribute(attconv_gemm_mma,
                         cudaFuncAttributeMaxDynamicSharedMemorySize, GEMM_SMEM);

    repack_w_kernel<<<NKS16 * 32 * 32 / 256, 256>>>(weight);
    sim_stats_kernel<<<dim3(T_ / 128, B_), 256>>>(embedding);
    sim_finalize_kernel<<<(B_ * T_ + 255) / 256, 256>>>();
    build_xs_kernel<<<dim3(NKP / 8, NT8, B_), 256>>>(feature);
    attconv_gemm_mma<<<dim3(8, 16, B_), 256, GEMM_SMEM>>>(out);
}

// round 16
// speedup vs baseline: 1.0591x; 1.0591x over previous
#include <cuda_runtime.h>
#include <cuda_fp16.h>
#include <math.h>
#include <cstdint>

// Problem constants
#define B_  8
#define C_  512
#define T_  4096
#define O_  512
#define CK_ 1536
#define EPS 1e-8f

#define NKS16 (CK_ / 16)      // 96 k16-steps
#define NKP   (CK_ / 32)      // 48 k32-steps
#define NT8   (T_ / 8)        // 512 n8 columns

#define DSTAGE 4              // cp.async ring depth per warp
#define STAGE_BYTES 2048      // 4 n8 * 32 lanes * 16B
#define GEMM_SMEM (8 * DSTAGE * STAGE_BYTES)   // 64 KB

// Scratch
__device__ float g_n2[B_ * T_];
__device__ float g_d [B_ * T_];
__device__ float g_s [B_ * 3 * T_];
__device__ uint4 g_wf[NKS16 * 32 * 32];             // W fp16 A-frags
__device__ uint4 g_xf[(size_t)B_ * NT8 * NKP * 32]; // Xs fp16 B-frags (~100MB)

__device__ __forceinline__ uint32_t packh2(float a, float b) {
    __half2 h = __floats2half2_rn(a, b);
    return *reinterpret_cast<uint32_t*>(&h);
}

__device__ __forceinline__ uint32_t smem_u32(const void* p) {
    uint32_t a;
    asm("{ .reg .u64 t; cvta.to.shared.u64 t, %1; cvt.u32.u64 %0, t; }"
        : "=r"(a) : "l"(p));
    return a;
}

__device__ __forceinline__ void mma_16816(float* d, const uint32_t* a,
                                          uint32_t b0, uint32_t b1) {
    asm volatile(
        "mma.sync.aligned.m16n8k16.row.col.f32.f16.f16.f32 "
        "{%0,%1,%2,%3}, {%4,%5,%6,%7}, {%8,%9}, {%0,%1,%2,%3};"
        : "+f"(d[0]), "+f"(d[1]), "+f"(d[2]), "+f"(d[3])
        : "r"(a[0]), "r"(a[1]), "r"(a[2]), "r"(a[3]), "r"(b0), "r"(b1));
}

// ---------------------------------------------------------------------------
// Kernel 0: repack W [O, CK] -> fp16 A-fragment order.
// ---------------------------------------------------------------------------
__global__ void repack_w_kernel(const float* __restrict__ w) {
    const int idx  = blockIdx.x * 256 + threadIdx.x;
    const int lane = idx & 31;
    const int m16  = (idx >> 5) & 31;
    const int ks   = idx >> 10;
    const uint32_t r  = m16 * 16 + (lane >> 2);
    const uint32_t k0 = ks * 16 + (lane & 3) * 2;
    const float* p0 = w + r * CK_ + k0;
    const float* p1 = p0 + 8 * CK_;
    uint4 v;
    v.x = packh2(p0[0], p0[1]);
    v.y = packh2(p1[0], p1[1]);
    v.z = packh2(p0[8], p0[9]);
    v.w = packh2(p1[8], p1[9]);
    g_wf[idx] = v;
}

// ---------------------------------------------------------------------------
// Kernel 1: column stats (R13-measured config). grid (T/32, B), block 256,
// C split 8-way. Halo via pre-decremented pointer (no unsigned underflow).
// ---------------------------------------------------------------------------
__global__ void sim_stats_kernel(const float* __restrict__ emb) {
    const int tsub = threadIdx.x & 31;
    const int cp   = threadIdx.x >> 5;
    const int t    = blockIdx.x * 32 + tsub;
    const int b    = blockIdx.y;
    const float* e = emb + (size_t)b * C_ * T_ + (uint32_t)cp * 64 * T_ + t;

    float n2 = 0.f, dd = 0.f;
    if (t > 0) {
        const float* em1 = e - 1;
        #pragma unroll 4
        for (uint32_t c = 0; c < 64; ++c) {
            float v  = e  [c * T_];
            float vp = em1[c * T_];
            n2 = fmaf(v, v,  n2);
            dd = fmaf(v, vp, dd);
        }
    } else {
        #pragma unroll 4
        for (uint32_t c = 0; c < 64; ++c) {
            float v = e[c * T_];
            n2 = fmaf(v, v, n2);
        }
    }
    __shared__ float sn[8][32], sd[8][32];
    sn[cp][tsub] = n2;
    sd[cp][tsub] = dd;
    __syncthreads();
    if (threadIdx.x < 32) {
        float a = 0.f, bs = 0.f;
        #pragma unroll
        for (int j = 0; j < 8; ++j) { a += sn[j][tsub]; bs += sd[j][tsub]; }
        g_n2[b * T_ + t] = a;
        g_d [b * T_ + t] = bs;
    }
}

// ---------------------------------------------------------------------------
// Kernel 2: finalize cosine sims (torch eps semantics).
// ---------------------------------------------------------------------------
__global__ void sim_finalize_kernel() {
    const int idx = blockIdx.x * 256 + threadIdx.x;
    if (idx >= B_ * T_) return;
    const int b = idx / T_;
    const int t = idx - b * T_;
    const float* n2 = g_n2 + b * T_;
    const float* d  = g_d  + b * T_;

    float nm    = fmaxf(sqrtf(n2[t]), EPS);
    float nprev = (t > 0)      ? fmaxf(sqrtf(n2[t - 1]), EPS) : EPS;
    float nnext = (t < T_ - 1) ? fmaxf(sqrtf(n2[t + 1]), EPS) : EPS;

    float* s = g_s + (size_t)b * 3 * T_;
    s[0 * T_ + t] = d[t] / (nm * nprev);
    s[1 * T_ + t] = n2[t] / (nm * nm);
    s[2 * T_ + t] = ((t < T_ - 1) ? d[t + 1] : 0.f) / (nm * nnext);
}

// ---------------------------------------------------------------------------
// Kernel 3: build Xs fragments (R15-measured: edge-specialized paths).
// ---------------------------------------------------------------------------
__global__ __launch_bounds__(256)
void build_xs_kernel(const float* __restrict__ feat) {
    const int lane = threadIdx.x & 31;
    const int kp   = blockIdx.x * 8 + (threadIdx.x >> 5);
    const int n8   = blockIdx.y;
    const int b    = blockIdx.z;
    const int col  = lane >> 2;
    const int q    = lane & 3;
    const int t    = n8 * 8 + col;

    const float* fb = feat + (size_t)b * C_ * T_;
    const float  sg = g_s[(size_t)b * 3 * T_ + (uint32_t)(kp >> 4) * T_ + t];

    int i0 = kp * 32 + 2 * q;
    uint32_t c  = (uint32_t)i0 / 3u;
    int      k3 = i0 - 3 * (int)c;

    float x[8];
    if (n8 != 0 && n8 != NT8 - 1) {
        // interior: t-1 >= 7, t+1 <= T-2 -> no bounds checks
        const float* fp = fb + (uint32_t)(t - 1);
        #pragma unroll
        for (int p = 0; p < 4; ++p) {
            x[2*p] = __ldg(fp + c * (uint32_t)T_ + (uint32_t)k3) * sg;
            uint32_t cb = c; int kb = k3 + 1;
            if (kb == 3) { kb = 0; ++cb; }
            x[2*p+1] = __ldg(fp + cb * (uint32_t)T_ + (uint32_t)kb) * sg;
            k3 += 2; c += 2;
            if (k3 >= 3) { k3 -= 3; ++c; }
        }
    } else {
        #pragma unroll
        for (int p = 0; p < 4; ++p) {
            {
                int tt = t + k3 - 1;
                x[2*p] = ((unsigned)tt < (unsigned)T_)
                       ? __ldg(&fb[c * (uint32_t)T_ + (uint32_t)tt]) * sg : 0.f;
            }
            {
                uint32_t cb = c; int kb = k3 + 1;
                if (kb == 3) { kb = 0; ++cb; }
                int tt = t + kb - 1;
                x[2*p+1] = ((unsigned)tt < (unsigned)T_)
                         ? __ldg(&fb[cb * (uint32_t)T_ + (uint32_t)tt]) * sg : 0.f;
            }
            k3 += 2; c += 2;
            if (k3 >= 3) { k3 -= 3; ++c; }
        }
    }
    uint4 v;
    v.x = packh2(x[0], x[1]);
    v.y = packh2(x[2], x[3]);
    v.z = packh2(x[4], x[5]);
    v.w = packh2(x[6], x[7]);
    const uint32_t oidx = (((uint32_t)b * NT8 + n8) * NKP + kp) * 32 + lane;
    g_xf[oidx] = v;
}

// ---------------------------------------------------------------------------
// Kernel 4: MMA GEMM with per-warp cp.async B pipeline (R13-measured).
// ---------------------------------------------------------------------------
__global__ __launch_bounds__(256, 2)
void attconv_gemm_mma(float* __restrict__ out) {
    extern __shared__ uint32_t smem[];
    const int tid  = threadIdx.x;
    const int wid  = tid >> 5;
    const int lane = tid & 31;
    const int b       = blockIdx.z;
    const int m16Base = blockIdx.x * 4;
    const int n8Base  = blockIdx.y * 32 + wid * 4;

    const uint4* aW = g_wf + lane;
    const uint4* xB = g_xf + (size_t)((((uint32_t)b * NT8 + n8Base) * NKP) * 32 + lane);

    const uint32_t swbase = smem_u32(smem) + (uint32_t)wid * (DSTAGE * STAGE_BYTES)
                          + (uint32_t)lane * 16;

    auto issueStage = [&](int kp, int stage) {
        #pragma unroll
        for (int ni = 0; ni < 4; ++ni) {
            const uint32_t dst = swbase + (uint32_t)stage * STAGE_BYTES + ni * 512;
            const void* src = (const void*)(xB + (uint32_t)(ni * NKP + kp) * 32);
            asm volatile("cp.async.cg.shared.global [%0], [%1], 16;"
                         :: "r"(dst), "l"(src));
        }
        asm volatile("cp.async.commit_group;" ::: "memory");
    };

    issueStage(0, 0);
    issueStage(1, 1);
    issueStage(2, 2);

    float acc[4][4][4] = {};

    for (int kp = 0; kp < NKP; ++kp) {
        const int kpn = (kp + 3 < NKP) ? kp + 3 : NKP - 1;
        issueStage(kpn, (kp + 3) & (DSTAGE - 1));
        asm volatile("cp.async.wait_group 3;" ::: "memory");

        uint4 bv[4];
        const uint32_t sb = swbase + (uint32_t)(kp & (DSTAGE - 1)) * STAGE_BYTES;
        #pragma unroll
        for (int ni = 0; ni < 4; ++ni)
            asm volatile("ld.shared.v4.b32 {%0,%1,%2,%3}, [%4];"
                         : "=r"(bv[ni].x), "=r"(bv[ni].y),
                           "=r"(bv[ni].z), "=r"(bv[ni].w)
                         : "r"(sb + ni * 512));

        #pragma unroll
        for (int ks = 0; ks < 2; ++ks) {
            const uint32_t ksg = 2 * kp + ks;
            uint32_t af[4][4];
            #pragma unroll
            for (int mi = 0; mi < 4; ++mi) {
                uint4 a = __ldg(aW + ((ksg * 32 + m16Base + mi) << 5));
                af[mi][0] = a.x; af[mi][1] = a.y; af[mi][2] = a.z; af[mi][3] = a.w;
            }
            #pragma unroll
            for (int mi = 0; mi < 4; ++mi)
                #pragma unroll
                for (int ni = 0; ni < 4; ++ni) {
                    const uint32_t b0 = ks ? bv[ni].z : bv[ni].x;
                    const uint32_t b1 = ks ? bv[ni].w : bv[ni].y;
                    mma_16816(acc[mi][ni], af[mi], b0, b1);
                }
        }
    }

    float* outb = out + (size_t)b * O_ * T_;
    #pragma unroll
    for (int mi = 0; mi < 4; ++mi) {
        const uint32_t row0 = (m16Base + mi) * 16 + (lane >> 2);
        #pragma unroll
        for (int ni = 0; ni < 4; ++ni) {
            const uint32_t col = (n8Base + ni) * 8 + (lane & 3) * 2;
            float2 v0 = make_float2(acc[mi][ni][0], acc[mi][ni][1]);
            float2 v1 = make_float2(acc[mi][ni][2], acc[mi][ni][3]);
            *reinterpret_cast<float2*>(&outb[row0 * (uint32_t)T_ + col])        = v0;
            *reinterpret_cast<float2*>(&outb[(row0 + 8) * (uint32_t)T_ + col])  = v1;
        }
    }
}

// ---------------------------------------------------------------------------
// Launch: inputs in metadata order: feature, embedding, weight
// ---------------------------------------------------------------------------
extern "C" void kernel_launch(void* const* d_in, const int* in_sizes, int n_in,
                              void* d_out, int out_size) {
    const float* feature   = (const float*)d_in[0];
    const float* embedding = (const float*)d_in[1];
    const float* weight    = (const float*)d_in[2];
    float* out = (float*)d_out;

    cudaFuncSetAttribute(attconv_gemm_mma,
                         cudaFuncAttributeMaxDynamicSharedMemorySize, GEMM_SMEM);

    repack_w_kernel<<<NKS16 * 32 * 32 / 256, 256>>>(weight);
    sim_stats_kernel<<<dim3(T_ / 32, B_), 256>>>(embedding);
    sim_finalize_kernel<<<(B_ * T_ + 255) / 256, 256>>>();
    build_xs_kernel<<<dim3(NKP / 8, NT8, B_), 256>>>(feature);
    attconv_gemm_mma<<<dim3(8, 16, B_), 256, GEMM_SMEM>>>(out);
}